// round 14
// baseline (speedup 1.0000x reference)
#include <cuda_runtime.h>
#include <cstdint>

#define TT 1024
#define BB 128
#define CC 256
#define SS 128
#define NTHR 192        // 6 warps (proven layout)
#define WIN 12          // steps per sync window == halo overlap 24 / 2 states per step
#define LOG2E 1.4426950408889634f
#define LN2F  0.6931471805599453f
#define NEG2  (-1.0e9f)

__device__ float g_loss[BB];
__device__ int   g_done;          // zero-init; nets to zero every launch

static __device__ __forceinline__ float fexp2(float x){ float y; asm("ex2.approx.ftz.f32 %0, %1;" : "=f"(y) : "f"(x)); return y; }
static __device__ __forceinline__ float flog2(float x){ float y; asm("lg2.approx.f32 %0, %1;" : "=f"(y) : "f"(x)); return y; }
static __device__ __forceinline__ void cp16(unsigned dst, const float* src){
  asm volatile("cp.async.cg.shared.global [%0], [%1], 16;" :: "r"(dst), "l"(src));
}
static __device__ __forceinline__ void cp_commit(){ asm volatile("cp.async.commit_group;"); }
template<int N> static __device__ __forceinline__ void cp_wait(){ asm volatile("cp.async.wait_group %0;" :: "n"(N)); }

// log2(1+u) on u in [0,1] via degree-6 Chebyshev-derived poly (max err ~2e-6).
// FFMA-pipe only: frees the MUFU LG2 slot.
static __device__ __forceinline__ float plog2_1p(float u){
  float x = fmaf(2.0f, u, -1.0f);
  float p = fmaf(x, -0.0003927f, 0.0013735f);
  p = fmaf(x, p, -0.0044142f);
  p = fmaf(x, p,  0.0177160f);
  p = fmaf(x, p, -0.0801556f);
  p = fmaf(x, p,  0.4809155f);
  p = fmaf(x, p,  0.5849625f);
  return p;
}

__global__ void __launch_bounds__(NTHR, 1) ctc_fwd(
    const float* __restrict__ lp, const int* __restrict__ y,
    const int* __restrict__ ilen, const int* __restrict__ tlen,
    float* __restrict__ out)
{
  __shared__ __align__(16) float rows[2 * WIN][CC]; // 24KB emission row ring, 2 windows
  __shared__ float alphA[280];                      // alpha exchange, double-buffered
  __shared__ float alphB[280];
  __shared__ float red[8];
  __shared__ int   lastblk;

  const int b    = blockIdx.x;
  const int tid  = threadIdx.x;
  const int w    = tid >> 5;
  const int lane = tid & 31;
  const int len  = ilen[b];
  const int tl   = tlen[b];

  const int bw = 40 * w;                 // strip base (even state)
  const int s0 = bw + 2 * lane;          // even state (blank)
  const int s1 = s0 + 1;                 // odd state (label)
  const int own_lo = w ? bw + 24 : 0;    // owned partition: [own_lo, bw+64)
  const bool ow0 = (s0 >= own_lo);
  const bool ow1 = (s1 >= own_lo);
  const bool lowcut = (w == 0) & (lane == 0);   // state 0 has no s-1 (even path only)

  // label class + skip flag for the odd state
  int idx  = s0 >> 1;                    // label index of s1
  int idxc = idx < SS ? idx : SS - 1;
  int im1  = idxc >= 1 ? idxc - 1 : 0;
  int cls  = y[b * SS + idxc];
  int clsp = y[b * SS + im1];
  bool skipok = (idx >= 1) && (idx < SS) && (cls != clsp);

  const float* gb = lp + (size_t)b * CC;
  const unsigned rows_u = (unsigned)__cvta_generic_to_shared(&rows[0][0]);

  // issue one 12-row window as one commit group (768 coalesced 16B chunks)
  auto issue_win = [&](int wt) {
    int bslot = ((wt / WIN) & 1) * WIN;
    #pragma unroll
    for (int k = 0; k < 4; ++k) {
      int c = tid + k * NTHR;            // 0..767
      int r   = c >> 6;
      int off = (c & 63) * 16;
      int row = wt + r;
      if (row < TT)
        cp16(rows_u + (unsigned)((bslot + r) * (CC * 4) + off),
             gb + (size_t)row * (BB * CC) + (off >> 2));
    }
    cp_commit();
  };

  // one unguarded step; even lse2 via EX2+poly (no LG2), odd lse3 select-form (2 EX2 + LG2)
  auto step = [&](float& a0, float& a1, int slot) {
    float sh = __shfl_up_sync(0xffffffffu, a1, 1);    // alpha[s0-1] == alpha[s1-2]
    // even (blank): lse2 = m0 + log2(1 + 2^(n0-m0)); log2(1+u) on FMA pipe
    float she = lowcut ? NEG2 : sh;
    float m0 = fmaxf(a0, she);
    float n0 = fminf(a0, she);
    float u  = fexp2(n0 - m0);
    float a0n = fmaf(rows[slot][0], LOG2E, m0) + plog2_1p(u);
    // odd: lse3 via FMNMX mid/min extraction (2 EX2 + 1 LG2)
    float sh2 = skipok ? sh : NEG2;
    float x  = fmaxf(a0, sh2);
    float yv = fminf(a0, sh2);
    float m1  = fmaxf(a1, x);
    float mid = fmaxf(fminf(a1, x), yv);
    float mn  = fminf(a1, yv);
    float sum = 1.0f + fexp2(mid - m1) + fexp2(mn - m1);
    float a1n = fmaf(rows[slot][cls], LOG2E, m1) + flog2(sum);
    a0 = a0n;
    a1 = a1n;
  };

  issue_win(0);
  cp_wait<0>();
  __syncthreads();

  // t=0 init (log2 domain): only global states 0 and 1 reachable
  float a0 = NEG2, a1 = NEG2;
  if (lowcut) {
    a0 = rows[0][0]   * LOG2E;
    a1 = rows[0][cls] * LOG2E;
  }

  // ---- window 0 (peeled): steps t=1..WIN-1, unguarded (len >= 768 > WIN) ----
  if (ow0) alphA[s0] = a0;
  if (ow1) alphA[s1] = a1;
  cp_wait<0>();
  __syncthreads();
  a0 = alphA[s0];
  a1 = alphA[s1];
  issue_win(WIN);
  #pragma unroll
  for (int j = 1; j < WIN; ++j) step(a0, a1, j);

  // ---- steady windows: all 12 steps valid, no guards ----
  int wi = 1;
  int wt = WIN;
  for (; wt + WIN <= len; wt += WIN, ++wi) {
    float* cur = (wi & 1) ? alphB : alphA;
    const int ws = (wi & 1) * WIN;
    if (ow0) cur[s0] = a0;
    if (ow1) cur[s1] = a1;
    cp_wait<0>();
    __syncthreads();
    a0 = cur[s0];                // strip reload first (critical path)
    a1 = cur[s1];
    issue_win(wt + WIN);         // then prefetch burst
    #pragma unroll
    for (int j = 0; j < WIN; ++j) step(a0, a1, ws + j);
  }

  // ---- tail window: rem in [0, WIN) steps, runtime-bounded, body unguarded ----
  const int rem = len - wt;
  if (rem > 0) {
    float* cur = (wi & 1) ? alphB : alphA;
    const int ws = (wi & 1) * WIN;
    if (ow0) cur[s0] = a0;
    if (ow1) cur[s1] = a1;
    cp_wait<0>();
    __syncthreads();
    a0 = cur[s0];
    a1 = cur[s1];
    #pragma unroll 1
    for (int j = 0; j < rem; ++j) step(a0, a1, ws + j);
  }

  // final: stage alpha_(len-1), extract loss
  __syncthreads();
  if (ow0) alphA[s0] = a0;
  if (ow1) alphA[s1] = a1;
  __syncthreads();

  if (tid == 0) {
    float ahi = alphA[2 * tl];
    float alo = alphA[2 * tl - 1];
    float m  = fmaxf(ahi, alo);
    float mn = fminf(ahi, alo);
    float ll2 = m + flog2(1.0f + fexp2(mn - m));
    float loss = -ll2 * LN2F;
    if (!(loss < 0.5e9f)) loss = 0.f;    // zero_infinity (also inf/nan)
    g_loss[b] = loss / (float)tl;
    __threadfence();
    int old = atomicAdd(&g_done, 1);
    int isl = (old == BB - 1);
    if (isl) g_done = 0;                 // reset for next graph replay
    lastblk = isl;
  }
  __syncthreads();

  if (lastblk) {                         // fused mean over batches in last block
    __threadfence();
    float v = (tid < BB) ? g_loss[tid] : 0.f;
    #pragma unroll
    for (int o = 16; o > 0; o >>= 1) v += __shfl_down_sync(0xffffffffu, v, o);
    if (lane == 0 && w < 4) red[w] = v;
    __syncthreads();
    if (tid == 0) out[0] = (red[0] + red[1] + red[2] + red[3]) * (1.0f / (float)BB);
  }
}

extern "C" void kernel_launch(void* const* d_in, const int* in_sizes, int n_in,
                              void* d_out, int out_size)
{
  const float* lp = (const float*)d_in[0];
  const int*   yy = (const int*)  d_in[1];
  const int*   il = (const int*)  d_in[2];
  const int*   tl = (const int*)  d_in[3];
  ctc_fwd<<<BB, NTHR>>>(lp, yy, il, tl, (float*)d_out);
}

// round 17
// speedup vs baseline: 1.0548x; 1.0548x over previous
#include <cuda_runtime.h>
#include <cstdint>

#define TT 1024
#define BB 128
#define CC 256
#define SS 128
#define NTHR 96         // 3 warps; 4 states per lane
#define WIN 20          // steps per sync window == strip overlap 40 / 2 states per step
#define LOG2E 1.4426950408889634f
#define LN2F  0.6931471805599453f
#define NEG2  (-1.0e9f)

__device__ float g_loss[BB];
__device__ int   g_done;          // zero-init; nets to zero every launch

static __device__ __forceinline__ float fexp2(float x){ float y; asm("ex2.approx.ftz.f32 %0, %1;" : "=f"(y) : "f"(x)); return y; }
static __device__ __forceinline__ float flog2(float x){ float y; asm("lg2.approx.f32 %0, %1;" : "=f"(y) : "f"(x)); return y; }
static __device__ __forceinline__ void cp16(unsigned dst, const float* src){
  asm volatile("cp.async.cg.shared.global [%0], [%1], 16;" :: "r"(dst), "l"(src));
}
static __device__ __forceinline__ void cp_commit(){ asm volatile("cp.async.commit_group;"); }
template<int N> static __device__ __forceinline__ void cp_wait(){ asm volatile("cp.async.wait_group %0;" :: "n"(N)); }

// log2(1+u) on u in [0,1], degree-6 poly (max err ~2e-6). FFMA pipe; frees MUFU.
static __device__ __forceinline__ float plog2_1p(float u){
  float x = fmaf(2.0f, u, -1.0f);
  float p = fmaf(x, -0.0003927f, 0.0013735f);
  p = fmaf(x, p, -0.0044142f);
  p = fmaf(x, p,  0.0177160f);
  p = fmaf(x, p, -0.0801556f);
  p = fmaf(x, p,  0.4809155f);
  p = fmaf(x, p,  0.5849625f);
  return p;
}

__global__ void __launch_bounds__(NTHR, 1) ctc_fwd(
    const float* __restrict__ lp, const int* __restrict__ y,
    const int* __restrict__ ilen, const int* __restrict__ tlen,
    float* __restrict__ out)
{
  __shared__ __align__(16) float rows[2 * WIN][CC]; // 40KB emission row ring, 2 windows
  __shared__ float alphA[312];                      // alpha exchange (covers phantom states)
  __shared__ float alphB[312];
  __shared__ float red[3];
  __shared__ int   lastblk;

  const int b    = blockIdx.x;
  const int tid  = threadIdx.x;
  const int w    = tid >> 5;
  const int lane = tid & 31;
  const int len  = ilen[b];
  const int tl   = tlen[b];

  // Strip layout: warp w covers states [88w, 88w+128); lane holds 4 consecutive.
  const int sb = 88 * w + 4 * lane;      // even state (blank)
  // owned partitions tile [0,260): w0 [0,128), w1 [128,216), w2 [216,260)
  const int olo = w ? 88 * w + 40 : 0;
  const int ohi = (w < 2) ? 88 * (w + 1) + 40 : 260;
  const bool p0 = (sb     >= olo) & (sb     < ohi);
  const bool p1 = (sb + 1 >= olo) & (sb + 1 < ohi);
  const bool p2 = (sb + 2 >= olo) & (sb + 2 < ohi);
  const bool p3 = (sb + 3 >= olo) & (sb + 3 < ohi);
  const bool lowcut = (w == 0) & (lane == 0);   // state 0 has no s-1

  // labels for odd states sb+1 (k1) and sb+3 (k3 = k1+1)
  const int k1 = sb >> 1;
  const int k3 = k1 + 1;
  const int k1c = k1 < SS ? k1 : SS - 1;
  const int k3c = k3 < SS ? k3 : SS - 1;
  const int cls1 = y[b * SS + k1c];
  const int cls3 = y[b * SS + k3c];
  const bool sk1 = (k1 >= 1) && (k1 < SS) && (cls1 != y[b * SS + k1c - 1]);
  const bool sk3 = (k3 < SS) && (k1 < SS) && (cls3 != cls1);

  const float* gb = lp + (size_t)b * CC;
  const unsigned rows_u = (unsigned)__cvta_generic_to_shared(&rows[0][0]);

  // issue one 20-row window as one commit group (1280 coalesced 16B chunks)
  auto issue_win = [&](int wt) {
    int bslot = ((wt / WIN) & 1) * WIN;
    #pragma unroll
    for (int k = 0; k < 14; ++k) {
      int c = tid + k * NTHR;            // 0..1279
      if (c < WIN * 64) {
        int r   = c >> 6;
        int off = (c & 63) * 16;
        int row = wt + r;
        if (row < TT)
          cp16(rows_u + (unsigned)((bslot + r) * (CC * 4) + off),
               gb + (size_t)row * (BB * CC) + (off >> 2));
      }
    }
    cp_commit();
  };

  // one unguarded step: 4 states per lane; cross-lane only via a3 -> next a0
  auto step = [&](float& a0, float& a1, float& a2, float& a3, int slot) {
    float sh = __shfl_up_sync(0xffffffffu, a3, 1);    // left lane's top state
    float eb = rows[slot][0]    * LOG2E;
    float e1 = rows[slot][cls1] * LOG2E;
    float e3 = rows[slot][cls3] * LOG2E;
    // s0 even: lse2(a0, sh)
    float she = lowcut ? NEG2 : sh;
    float m0 = fmaxf(a0, she);
    float n0 = fminf(a0, she);
    float r0 = (m0 + eb) + plog2_1p(fexp2(n0 - m0));
    // s1 odd: lse3(a1, a0, sh if skip) via FMNMX mid/min
    float q1 = sk1 ? sh : NEG2;
    float x1 = fmaxf(a0, q1), y1 = fminf(a0, q1);
    float M1 = fmaxf(a1, x1);
    float d1 = fmaxf(fminf(a1, x1), y1);
    float n1 = fminf(a1, y1);
    float r1 = (M1 + e1) + flog2(1.0f + fexp2(d1 - M1) + fexp2(n1 - M1));
    // s2 even: lse2(a2, a1)
    float m2 = fmaxf(a2, a1);
    float n2 = fminf(a2, a1);
    float r2 = (m2 + eb) + plog2_1p(fexp2(n2 - m2));
    // s3 odd: lse3(a3, a2, a1 if skip)
    float q3 = sk3 ? a1 : NEG2;
    float x3 = fmaxf(a2, q3), y3 = fminf(a2, q3);
    float M3 = fmaxf(a3, x3);
    float d3 = fmaxf(fminf(a3, x3), y3);
    float n3 = fminf(a3, y3);
    float r3 = (M3 + e3) + flog2(1.0f + fexp2(d3 - M3) + fexp2(n3 - M3));
    a0 = r0; a1 = r1; a2 = r2; a3 = r3;
  };

  issue_win(0);
  cp_wait<0>();
  __syncthreads();

  // t=0 init (log2 domain): only global states 0 and 1 reachable
  float a0 = NEG2, a1 = NEG2, a2 = NEG2, a3 = NEG2;
  if (lowcut) {
    a0 = rows[0][0]    * LOG2E;
    a1 = rows[0][cls1] * LOG2E;
  }

  // ---- window 0 (peeled): steps t=1..WIN-1, unguarded (len >= 768 > WIN) ----
  if (p0) alphA[sb]     = a0;
  if (p1) alphA[sb + 1] = a1;
  if (p2) alphA[sb + 2] = a2;
  if (p3) alphA[sb + 3] = a3;
  cp_wait<0>();
  __syncthreads();
  a0 = alphA[sb];
  a1 = alphA[sb + 1];
  a2 = alphA[sb + 2];
  a3 = alphA[sb + 3];
  issue_win(WIN);
  #pragma unroll
  for (int j = 1; j < WIN; ++j) step(a0, a1, a2, a3, j);

  // ---- steady windows: all WIN steps valid, no guards ----
  int wi = 1;
  int wt = WIN;
  for (; wt + WIN <= len; wt += WIN, ++wi) {
    float* cur = (wi & 1) ? alphB : alphA;
    const int ws = (wi & 1) * WIN;
    if (p0) cur[sb]     = a0;
    if (p1) cur[sb + 1] = a1;
    if (p2) cur[sb + 2] = a2;
    if (p3) cur[sb + 3] = a3;
    cp_wait<0>();
    __syncthreads();
    a0 = cur[sb];                // strip reload first (critical path)
    a1 = cur[sb + 1];
    a2 = cur[sb + 2];
    a3 = cur[sb + 3];
    issue_win(wt + WIN);         // then prefetch burst
    #pragma unroll
    for (int j = 0; j < WIN; ++j) step(a0, a1, a2, a3, ws + j);
  }

  // ---- tail window: rem in [0, WIN) steps, runtime-bounded, body unguarded ----
  const int rem = len - wt;
  if (rem > 0) {
    float* cur = (wi & 1) ? alphB : alphA;
    const int ws = (wi & 1) * WIN;
    if (p0) cur[sb]     = a0;
    if (p1) cur[sb + 1] = a1;
    if (p2) cur[sb + 2] = a2;
    if (p3) cur[sb + 3] = a3;
    cp_wait<0>();
    __syncthreads();
    a0 = cur[sb];
    a1 = cur[sb + 1];
    a2 = cur[sb + 2];
    a3 = cur[sb + 3];
    #pragma unroll 1
    for (int j = 0; j < rem; ++j) step(a0, a1, a2, a3, ws + j);
  }

  // final: stage alpha_(len-1), extract loss
  __syncthreads();
  if (p0) alphA[sb]     = a0;
  if (p1) alphA[sb + 1] = a1;
  if (p2) alphA[sb + 2] = a2;
  if (p3) alphA[sb + 3] = a3;
  __syncthreads();

  if (tid == 0) {
    float ahi = alphA[2 * tl];
    float alo = alphA[2 * tl - 1];
    float m  = fmaxf(ahi, alo);
    float mn = fminf(ahi, alo);
    float ll2 = m + flog2(1.0f + fexp2(mn - m));
    float loss = -ll2 * LN2F;
    if (!(loss < 0.5e9f)) loss = 0.f;    // zero_infinity (also inf/nan)
    g_loss[b] = loss / (float)tl;
    __threadfence();
    int old = atomicAdd(&g_done, 1);
    int isl = (old == BB - 1);
    if (isl) g_done = 0;                 // reset for next graph replay
    lastblk = isl;
  }
  __syncthreads();

  if (lastblk) {                         // fused mean over batches in last block
    __threadfence();
    float v = g_loss[tid];               // 96 threads cover 128 entries
    if (tid < BB - NTHR) v += g_loss[NTHR + tid];
    #pragma unroll
    for (int o = 16; o > 0; o >>= 1) v += __shfl_down_sync(0xffffffffu, v, o);
    if (lane == 0) red[w] = v;
    __syncthreads();
    if (tid == 0) out[0] = (red[0] + red[1] + red[2]) * (1.0f / (float)BB);
  }
}

extern "C" void kernel_launch(void* const* d_in, const int* in_sizes, int n_in,
                              void* d_out, int out_size)
{
  const float* lp = (const float*)d_in[0];
  const int*   yy = (const int*)  d_in[1];
  const int*   il = (const int*)  d_in[2];
  const int*   tl = (const int*)  d_in[3];
  ctc_fwd<<<BB, NTHR>>>(lp, yy, il, tl, (float*)d_out);
}